// round 5
// baseline (speedup 1.0000x reference)
#include <cuda_runtime.h>
#include <cuda_bf16.h>
#include <cstdint>

// out = tanh( Xa @ W1'^T + T[b] ),  T = s @ W2^T,  s[b] = sum_a x[b,a,:]
// W1' = Wh - Wc/7, W2 = Wc/7.  Split-bf16 HMMA; A-fragments built directly
// from global fp32 (no A smem), W1 h/l fragments resident in registers.
// Tile: 128 agent rows (16 batch rows); warp (g=w>>1, c=w&1):
// rows {16g, 64+16g}, cols 32c..32c+31.

#define NTILES 4096
#define TSTRIDE 68

#define OFF_W2H 0
#define OFF_W2L 8192
#define OFF_SH  16384   /* 2 x 2KB */
#define OFF_SL  20480   /* 2 x 2KB */
#define OFF_T   24576   /* 16*68*4 */
#define SMEM_SZ 28928

__device__ __forceinline__ uint32_t smem_u32(const void* p) {
    uint32_t a;
    asm("{ .reg .u64 t; cvta.to.shared.u64 t, %1; cvt.u32.u64 %0, t; }"
        : "=r"(a) : "l"(p));
    return a;
}

__device__ __forceinline__ uint32_t pack_bf16(float a, float b) {
    __nv_bfloat162 t = __float22bfloat162_rn(make_float2(a, b));
    return *reinterpret_cast<uint32_t*>(&t);
}

__device__ __forceinline__ void mma_bf16(float* c, const uint32_t* a,
                                         uint32_t b0, uint32_t b1) {
    asm volatile(
        "mma.sync.aligned.m16n8k16.row.col.f32.bf16.bf16.f32 "
        "{%0,%1,%2,%3}, {%4,%5,%6,%7}, {%8,%9}, {%0,%1,%2,%3};"
        : "+f"(c[0]), "+f"(c[1]), "+f"(c[2]), "+f"(c[3])
        : "r"(a[0]), "r"(a[1]), "r"(a[2]), "r"(a[3]), "r"(b0), "r"(b1));
}

__device__ __forceinline__ void ldsm4(uint32_t* r, uint32_t addr) {
    asm volatile(
        "ldmatrix.sync.aligned.m8n8.x4.shared.b16 {%0,%1,%2,%3}, [%4];"
        : "=r"(r[0]), "=r"(r[1]), "=r"(r[2]), "=r"(r[3]) : "r"(addr));
}

__device__ __forceinline__ void ldsm2(uint32_t* r, uint32_t addr) {
    asm volatile(
        "ldmatrix.sync.aligned.m8n8.x2.shared.b16 {%0,%1}, [%2];"
        : "=r"(r[0]), "=r"(r[1]) : "r"(addr));
}

__device__ __forceinline__ float tanh_fast(float y) {
    float r;
    asm("tanh.approx.f32 %0, %1;" : "=f"(r) : "f"(y));
    return r;
}

// Load the 8 fp32 for one m16k16 A-fragment step (4 LDG.64).
__device__ __forceinline__ void load_step(float2* f, const float* xt, int g,
                                          int p, int q, int j) {
    int ks = p & 3, bt = p >> 2;
    const float* b =
        xt + (size_t)(((g << 4) + (bt << 6) + q) * 64 + (ks << 4) + (j << 1));
    f[0] = *(const float2*)b;
    f[1] = *(const float2*)(b + 8 * 64);
    f[2] = *(const float2*)(b + 8);
    f[3] = *(const float2*)(b + 8 * 64 + 8);
}

__device__ __forceinline__ void cvt_frag(const float2* f, uint32_t* ah,
                                         uint32_t* al) {
#pragma unroll
    for (int i = 0; i < 4; i++) {
        float h0 = __bfloat162float(__float2bfloat16(f[i].x));
        float h1 = __bfloat162float(__float2bfloat16(f[i].y));
        ah[i] = pack_bf16(h0, h1);
        al[i] = pack_bf16(f[i].x - h0, f[i].y - h1);
    }
}

__global__ void __launch_bounds__(256, 2)
comm_v5(const float* __restrict__ x, const float* __restrict__ Wh,
        const float* __restrict__ Wc, float* __restrict__ out) {
    __shared__ __align__(16) char sm[SMEM_SZ];
    const uint32_t sb = smem_u32(sm);

    const int tid = threadIdx.x;
    const int w = tid >> 5;
    const int lane = tid & 31;
    const int g = w >> 1, c = w & 1;
    const int q = lane >> 2, j = lane & 3;

    // ---- init W2 = Wc/7 into smem as bf16 hi/lo, swizzled K-major ----
    for (int i = tid; i < 4096; i += 256) {
        int n = i >> 6, k = i & 63;
        float v = Wc[(n << 6) + k] * (1.0f / 7.0f);
        __nv_bfloat16 h = __float2bfloat16(v);
        __nv_bfloat16 l = __float2bfloat16(v - __bfloat162float(h));
        uint32_t off = (n << 7) + ((((k >> 3) ^ (n & 7)) << 4)) + ((k & 7) << 1);
        *(__nv_bfloat16*)(sm + OFF_W2H + off) = h;
        *(__nv_bfloat16*)(sm + OFF_W2L + off) = l;
    }

    // ---- init W1' B-fragments in registers: bWh/bWl[ks][nb][2] ----
    uint32_t bWh[4][4][2], bWl[4][4][2];
#pragma unroll
    for (int ks = 0; ks < 4; ks++) {
#pragma unroll
        for (int nb = 0; nb < 4; nb++) {
            int n = (c << 5) + (nb << 3) + q;
            int k0 = (ks << 4) + (j << 1);
            float w00 = Wh[n * 64 + k0]     - Wc[n * 64 + k0]     * (1.0f / 7.0f);
            float w01 = Wh[n * 64 + k0 + 1] - Wc[n * 64 + k0 + 1] * (1.0f / 7.0f);
            float w10 = Wh[n * 64 + k0 + 8] - Wc[n * 64 + k0 + 8] * (1.0f / 7.0f);
            float w11 = Wh[n * 64 + k0 + 9] - Wc[n * 64 + k0 + 9] * (1.0f / 7.0f);
            float h00 = __bfloat162float(__float2bfloat16(w00));
            float h01 = __bfloat162float(__float2bfloat16(w01));
            float h10 = __bfloat162float(__float2bfloat16(w10));
            float h11 = __bfloat162float(__float2bfloat16(w11));
            bWh[ks][nb][0] = pack_bf16(h00, h01);
            bWh[ks][nb][1] = pack_bf16(h10, h11);
            bWl[ks][nb][0] = pack_bf16(w00 - h00, w01 - h01);
            bWl[ks][nb][1] = pack_bf16(w10 - h10, w11 - h11);
        }
    }
    __syncthreads();

    // ---- invariants ----
    const int arow = lane & 15, ahi = lane >> 4, arow7 = arow & 7;
    const int brow2 = (w << 3) + (lane & 7);
    const int g2 = (lane >> 3) & 1;
    const uint32_t bb2 = (uint32_t)(brow2 << 7);
    const int b72 = brow2 & 7;
    const int b16 = tid >> 4, dc = tid & 15;
    const uint32_t so_off =
        (uint32_t)(b16 << 7) + ((((dc >> 1) ^ (b16 & 7))) << 4) + ((dc & 1) << 3);
    float* Tp = (float*)(sm + OFF_T);

    int t = blockIdx.x;
    const int stride = gridDim.x;
    int jb = 0;

    for (;;) {
        const float* xt = x + (size_t)t * 8192;
        const uint32_t sB = (uint32_t)((jb & 1) << 11);  // s double-buffer

        // ---- s-pass: s[b] = sum_a x[b,a,:] (fp32), split-bf16 STS ----
        {
            const float4* xp =
                (const float4*)(xt + (size_t)(b16 * 8) * 64 + dc * 4);
            float4 sv = xp[0];
#pragma unroll
            for (int a = 1; a < 8; a++) {
                float4 v = xp[a * 16];
                sv.x += v.x; sv.y += v.y; sv.z += v.z; sv.w += v.w;
            }
            float h0 = __bfloat162float(__float2bfloat16(sv.x));
            float h1 = __bfloat162float(__float2bfloat16(sv.y));
            float h2 = __bfloat162float(__float2bfloat16(sv.z));
            float h3 = __bfloat162float(__float2bfloat16(sv.w));
            *(uint2*)(sm + OFF_SH + sB + so_off) =
                make_uint2(pack_bf16(h0, h1), pack_bf16(h2, h3));
            *(uint2*)(sm + OFF_SL + sB + so_off) =
                make_uint2(pack_bf16(sv.x - h0, sv.y - h1),
                           pack_bf16(sv.z - h2, sv.w - h3));
        }
        __syncthreads();

        // ---- T-GEMM: warp's 8-col slice of s @ W2^T (3 splits) ----
        {
            float accT[4] = {0.f, 0.f, 0.f, 0.f};
            const uint32_t bsh = sb + OFF_SH + sB, bsl = sb + OFF_SL + sB;
#pragma unroll
            for (int ks = 0; ks < 4; ks++) {
                uint32_t sa = (uint32_t)(arow << 7) +
                              ((((2 * ks + ahi) ^ arow7)) << 4);
                uint32_t b2a = bb2 + ((((2 * ks + g2) ^ b72)) << 4);
                uint32_t sh_[4], sl_[4], b2h[2], b2l[2];
                ldsm4(sh_, bsh + sa);
                ldsm2(b2h, sb + OFF_W2H + b2a);
                mma_bf16(accT, sh_, b2h[0], b2h[1]);
                ldsm2(b2l, sb + OFF_W2L + b2a);
                mma_bf16(accT, sh_, b2l[0], b2l[1]);
                ldsm4(sl_, bsl + sa);
                mma_bf16(accT, sl_, b2h[0], b2h[1]);
            }
            int tr = lane >> 2, tc = (w << 3) + ((lane & 3) << 1);
            *(float2*)(Tp + tr * TSTRIDE + tc) = make_float2(accT[0], accT[1]);
            *(float2*)(Tp + (tr + 8) * TSTRIDE + tc) =
                make_float2(accT[2], accT[3]);
        }

        // ---- Y1: 8 steps (bt,ks); A-frags direct from global, B in regs ----
        float accY[2][4][4] = {};
        {
            float2 fbuf[2][4];
            load_step(fbuf[0], xt, g, 0, q, j);
#pragma unroll
            for (int p = 0; p < 8; p++) {
                if (p < 7) load_step(fbuf[(p + 1) & 1], xt, g, p + 1, q, j);
                uint32_t ah[4], al[4];
                cvt_frag(fbuf[p & 1], ah, al);
                int bt = p >> 2, ks = p & 3;
#pragma unroll
                for (int nb = 0; nb < 4; nb++)
                    mma_bf16(accY[bt][nb], ah, bWh[ks][nb][0], bWh[ks][nb][1]);
#pragma unroll
                for (int nb = 0; nb < 4; nb++)
                    mma_bf16(accY[bt][nb], ah, bWl[ks][nb][0], bWl[ks][nb][1]);
#pragma unroll
                for (int nb = 0; nb < 4; nb++)
                    mma_bf16(accY[bt][nb], al, bWh[ks][nb][0], bWh[ks][nb][1]);
            }
        }
        __syncthreads();  // T complete before epilogue reads

        // ---- epilogue: add T, tanh, store ----
#pragma unroll
        for (int bt = 0; bt < 2; bt++) {
#pragma unroll
            for (int h = 0; h < 2; h++) {
                int bb = 2 * g + 8 * bt + h;
                const float* Trow = Tp + bb * TSTRIDE + (c << 5) + (j << 1);
                int R = t * 128 + (g << 4) + (bt << 6) + (h << 3) + q;
                float* op = out + (size_t)R * 64 + (c << 5) + (j << 1);
#pragma unroll
                for (int nb = 0; nb < 4; nb++) {
                    float2 tv = *(const float2*)(Trow + (nb << 3));
                    float y0 = accY[bt][nb][2 * h] + tv.x;
                    float y1 = accY[bt][nb][2 * h + 1] + tv.y;
                    *(float2*)(op + (nb << 3)) =
                        make_float2(tanh_fast(y0), tanh_fast(y1));
                }
            }
        }

        t += stride;
        if (t >= NTILES) break;
        ++jb;
    }
}

extern "C" void kernel_launch(void* const* d_in, const int* in_sizes, int n_in,
                              void* d_out, int out_size) {
    const float* x  = (const float*)d_in[0];
    const float* Wh = (const float*)d_in[1];
    const float* Wc = (const float*)d_in[2];
    float* out = (float*)d_out;

    int dev = 0, sms = 148;
    cudaGetDevice(&dev);
    cudaDeviceGetAttribute(&sms, cudaDevAttrMultiProcessorCount, dev);

    comm_v5<<<2 * sms, 256>>>(x, Wh, Wc, out);
}